// round 7
// baseline (speedup 1.0000x reference)
#include <cuda_runtime.h>
#include <cuda_bf16.h>
#include <math.h>

// ---------------- Problem constants ----------------
#define S_LEN 2048
#define D_MOD 768
#define N_HEADS 12
#define HDIM 64
#define QT 64
#define KW 192

// ---------------- Split-bf16 GEMM constants ----------------
#define GK 2304            // tripled K: [hi | lo | hi]
#define NCHUNK 36          // GK / 64
#define CHUNK_K 64

// ---------------- Scratch (no cudaMalloc allowed) ----------------
__device__ float g_Q[S_LEN * D_MOD];
__device__ float g_K[S_LEN * D_MOD];
__device__ float g_V[S_LEN * D_MOD];
__device__ float g_ctx[S_LEN * D_MOD];
__device__ __align__(1024) __nv_bfloat16 g_Apk[3][S_LEN * GK];
__device__ __align__(1024) __nv_bfloat16 g_Bpk[3][D_MOD * GK];

// ---------------- PTX helpers (base sm_103-safe: sm_80 era) ----------------
__device__ __forceinline__ unsigned smem_u32(const void* p) {
    unsigned a;
    asm("{ .reg .u64 t; cvta.to.shared.u64 t, %1; cvt.u32.u64 %0, t; }"
        : "=r"(a) : "l"(p));
    return a;
}
__device__ __forceinline__ void cp_async16(unsigned saddr, const void* gptr) {
    asm volatile("cp.async.cg.shared.global [%0], [%1], 16;"
                 :: "r"(saddr), "l"(gptr));
}
__device__ __forceinline__ void cp_commit() {
    asm volatile("cp.async.commit_group;");
}
__device__ __forceinline__ void cp_wait1() {
    asm volatile("cp.async.wait_group 1;");
}
__device__ __forceinline__ void ldsm_x4(unsigned* r, unsigned addr) {
    asm volatile("ldmatrix.sync.aligned.m8n8.x4.shared.b16 {%0,%1,%2,%3}, [%4];"
                 : "=r"(r[0]), "=r"(r[1]), "=r"(r[2]), "=r"(r[3]) : "r"(addr));
}
__device__ __forceinline__ void mma16816(float* c, const unsigned* a, const unsigned* b) {
    asm volatile(
        "mma.sync.aligned.m16n8k16.row.col.f32.bf16.bf16.f32 "
        "{%0,%1,%2,%3}, {%4,%5,%6,%7}, {%8,%9}, {%0,%1,%2,%3};"
        : "+f"(c[0]), "+f"(c[1]), "+f"(c[2]), "+f"(c[3])
        : "r"(a[0]), "r"(a[1]), "r"(a[2]), "r"(a[3]), "r"(b[0]), "r"(b[1]));
}
__device__ __forceinline__ unsigned pack2(__nv_bfloat16 a, __nv_bfloat16 b) {
    __nv_bfloat162 t = __halves2bfloat162(a, b);
    return *(unsigned*)&t;
}

// ---------------------------------------------------------------------------
// Pack A (up to 3 inputs): fp32 [2048x768] -> bf16 [2048][2304] = [hi|lo|hi]
// Vectorized: each thread converts 4 k's, 8-byte stores per region.
// ---------------------------------------------------------------------------
__global__ __launch_bounds__(256) void pack_A3_kernel(
    const float* __restrict__ A0, const float* __restrict__ A1,
    const float* __restrict__ A2,
    __nv_bfloat16* __restrict__ O0, __nv_bfloat16* __restrict__ O1,
    __nv_bfloat16* __restrict__ O2)
{
    const int z = blockIdx.y;
    const float* A = (z == 0) ? A0 : (z == 1) ? A1 : A2;
    __nv_bfloat16* O = (z == 0) ? O0 : (z == 1) ? O1 : O2;

    int g = blockIdx.x * 256 + threadIdx.x;     // < 2048*192
    int m = g / 192, kq = (g - m * 192) * 4;
    float4 v = *(const float4*)&A[(size_t)m * D_MOD + kq];

    __nv_bfloat16 h0 = __float2bfloat16(v.x), h1 = __float2bfloat16(v.y);
    __nv_bfloat16 h2 = __float2bfloat16(v.z), h3 = __float2bfloat16(v.w);
    __nv_bfloat16 l0 = __float2bfloat16(v.x - __bfloat162float(h0));
    __nv_bfloat16 l1 = __float2bfloat16(v.y - __bfloat162float(h1));
    __nv_bfloat16 l2 = __float2bfloat16(v.z - __bfloat162float(h2));
    __nv_bfloat16 l3 = __float2bfloat16(v.w - __bfloat162float(h3));

    uint2 hw = make_uint2(pack2(h0, h1), pack2(h2, h3));
    uint2 lw = make_uint2(pack2(l0, l1), pack2(l2, l3));
    __nv_bfloat16* row = O + (size_t)m * GK;
    *(uint2*)&row[kq]        = hw;
    *(uint2*)&row[kq + 768]  = lw;
    *(uint2*)&row[kq + 1536] = hw;
}

// ---------------------------------------------------------------------------
// Pack W (up to 3 weights): fp32 [K=768][N=768] transposed ->
// bf16 [768 n][2304 k] = [hi|hi|lo], via 32x32 smem transpose, 8-byte stores.
// ---------------------------------------------------------------------------
__global__ __launch_bounds__(256) void pack_W3_kernel(
    const float* __restrict__ W0, const float* __restrict__ W1,
    const float* __restrict__ W2,
    __nv_bfloat16* __restrict__ O0, __nv_bfloat16* __restrict__ O1,
    __nv_bfloat16* __restrict__ O2)
{
    const int z = blockIdx.z;
    const float* W = (z == 0) ? W0 : (z == 1) ? W1 : W2;
    __nv_bfloat16* O = (z == 0) ? O0 : (z == 1) ? O1 : O2;

    __shared__ float t[32][33];
    const int tx = threadIdx.x & 31;
    const int ty = threadIdx.x >> 5;           // 0..7
    const int k0 = blockIdx.y * 32;
    const int n0 = blockIdx.x * 32;
#pragma unroll
    for (int i = 0; i < 4; i++)
        t[ty + i * 8][tx] = W[(size_t)(k0 + ty + i * 8) * D_MOD + n0 + tx];
    __syncthreads();

    const int nl = threadIdx.x >> 3;           // 0..31
    const int kg = (threadIdx.x & 7) * 4;      // 0..28
    float v0 = t[kg + 0][nl], v1 = t[kg + 1][nl];
    float v2 = t[kg + 2][nl], v3 = t[kg + 3][nl];

    __nv_bfloat16 h0 = __float2bfloat16(v0), h1 = __float2bfloat16(v1);
    __nv_bfloat16 h2 = __float2bfloat16(v2), h3 = __float2bfloat16(v3);
    __nv_bfloat16 l0 = __float2bfloat16(v0 - __bfloat162float(h0));
    __nv_bfloat16 l1 = __float2bfloat16(v1 - __bfloat162float(h1));
    __nv_bfloat16 l2 = __float2bfloat16(v2 - __bfloat162float(h2));
    __nv_bfloat16 l3 = __float2bfloat16(v3 - __bfloat162float(h3));

    uint2 hw = make_uint2(pack2(h0, h1), pack2(h2, h3));
    uint2 lw = make_uint2(pack2(l0, l1), pack2(l2, l3));
    __nv_bfloat16* row = O + (size_t)(n0 + nl) * GK + k0 + kg;
    *(uint2*)&row[0]    = hw;
    *(uint2*)&row[768]  = hw;
    *(uint2*)&row[1536] = lw;
}

// ---------------------------------------------------------------------------
// HMMA GEMM (batched over blockIdx.z): C = A' @ B'^T + bias (fp32 accum)
// CTA 128x128, 8 warps (warp tile 64x32), K-chunk 64, 3-stage cp.async.
// ---------------------------------------------------------------------------
#define GSTAGES 3
#define STAGE_BYTES 32768   // A 16KB + B 16KB

__global__ __launch_bounds__(256, 2) void gemm_mma_kernel(
    const __nv_bfloat16* __restrict__ a0, const __nv_bfloat16* __restrict__ a1,
    const __nv_bfloat16* __restrict__ a2,
    const __nv_bfloat16* __restrict__ b0, const __nv_bfloat16* __restrict__ b1,
    const __nv_bfloat16* __restrict__ b2,
    const float* __restrict__ bias0, const float* __restrict__ bias1,
    const float* __restrict__ bias2,
    float* __restrict__ c0, float* __restrict__ c1, float* __restrict__ c2)
{
    const int z = blockIdx.z;
    const __nv_bfloat16* Apk = (z == 0) ? a0 : (z == 1) ? a1 : a2;
    const __nv_bfloat16* Bpk = (z == 0) ? b0 : (z == 1) ? b1 : b2;
    const float* bias = (z == 0) ? bias0 : (z == 1) ? bias1 : bias2;
    float* C = (z == 0) ? c0 : (z == 1) ? c1 : c2;

    extern __shared__ char smem[];
    const unsigned sb = smem_u32(smem);

    const int tid  = threadIdx.x;
    const int wid  = tid >> 5;
    const int lane = tid & 31;
    const int wm   = wid & 1;
    const int wn   = wid >> 1;
    const int mBase = blockIdx.y * 128;
    const int nBase = blockIdx.x * 128;

    const __nv_bfloat16* aSrc = Apk + (size_t)mBase * GK;
    const __nv_bfloat16* bSrc = Bpk + (size_t)nBase * GK;

    const int lrow = tid >> 1;
    const int lch0 = (tid & 1) << 2;
    auto load_stage = [&](int stage, int chunk) {
        unsigned sA = sb + stage * STAGE_BYTES;
        unsigned sB = sA + 16384;
        const __nv_bfloat16* ga = aSrc + (size_t)lrow * GK + chunk * CHUNK_K + lch0 * 8;
        const __nv_bfloat16* gb = bSrc + (size_t)lrow * GK + chunk * CHUNK_K + lch0 * 8;
        unsigned rbase = lrow * 128;
        unsigned rx = lrow & 7;
#pragma unroll
        for (int c = 0; c < 4; c++) {
            unsigned swoff = rbase + (((lch0 + c) ^ rx) << 4);
            cp_async16(sA + swoff, ga + c * 8);
            cp_async16(sB + swoff, gb + c * 8);
        }
    };

    float acc[4][4][4];
#pragma unroll
    for (int i = 0; i < 4; i++)
#pragma unroll
        for (int j = 0; j < 4; j++)
#pragma unroll
            for (int r = 0; r < 4; r++) acc[i][j][r] = 0.f;

    load_stage(0, 0); cp_commit();
    load_stage(1, 1); cp_commit();

    const int arow_l = wm * 64 + (lane & 15);
    const int asel   = lane >> 4;
    const int brow_l = wn * 32 + ((lane & 16) ? 8 : 0) + (lane & 7);
    const int bsel   = (lane >> 3) & 1;

    for (int c = 0; c < NCHUNK; c++) {
        cp_wait1();
        __syncthreads();
        if (c + 2 < NCHUNK) { load_stage((c + 2) % GSTAGES, c + 2); cp_commit(); }
        else                { cp_commit(); }

        unsigned sA = sb + (c % GSTAGES) * STAGE_BYTES;
        unsigned sB = sA + 16384;

#pragma unroll
        for (int ks = 0; ks < 4; ks++) {
            unsigned afr[4][4];
#pragma unroll
            for (int i = 0; i < 4; i++) {
                int row = arow_l + i * 16;
                int ch = 2 * ks + asel;
                ldsm_x4(afr[i], sA + row * 128 + ((ch ^ (row & 7)) << 4));
            }
            unsigned bfr[2][4];
#pragma unroll
            for (int p = 0; p < 2; p++) {
                int row = brow_l + p * 16;
                int ch = 2 * ks + bsel;
                ldsm_x4(bfr[p], sB + row * 128 + ((ch ^ (row & 7)) << 4));
            }
#pragma unroll
            for (int i = 0; i < 4; i++) {
#pragma unroll
                for (int p = 0; p < 2; p++) {
                    mma16816(acc[i][2 * p],     afr[i], &bfr[p][0]);
                    mma16816(acc[i][2 * p + 1], afr[i], &bfr[p][2]);
                }
            }
        }
    }

#pragma unroll
    for (int i = 0; i < 4; i++) {
        int row = mBase + wm * 64 + i * 16 + (lane >> 2);
#pragma unroll
        for (int j = 0; j < 4; j++) {
            int col = nBase + wn * 32 + j * 8 + (lane & 3) * 2;
            float2 b2 = *(const float2*)&bias[col];
            float2 o0 = make_float2(acc[i][j][0] + b2.x, acc[i][j][1] + b2.y);
            float2 o1 = make_float2(acc[i][j][2] + b2.x, acc[i][j][3] + b2.y);
            *(float2*)&C[(size_t)row * D_MOD + col] = o0;
            *(float2*)&C[(size_t)(row + 8) * D_MOD + col] = o1;
        }
    }
}

// ---------------------------------------------------------------------------
// Sliding-window attention (unchanged: ~65us)
// ---------------------------------------------------------------------------
#define QT_STRIDE 68
#define KT_STRIDE 196
#define VS_STRIDE 64
#define PT_STRIDE 68
#define ATTN_SMEM_FLOATS (HDIM*QT_STRIDE + HDIM*KT_STRIDE + KW*VS_STRIDE + KW*PT_STRIDE)

__global__ __launch_bounds__(256) void attn_kernel(
    const float* __restrict__ Q, const float* __restrict__ K,
    const float* __restrict__ V, float* __restrict__ ctx)
{
    extern __shared__ float sm[];
    float* Qt = sm;
    float* Kt = Qt + HDIM * QT_STRIDE;
    float* Vs = Kt + HDIM * KT_STRIDE;
    float* Pt = Vs + KW * VS_STRIDE;

    const int qt = blockIdx.x;
    const int h  = blockIdx.y;
    const int qbase = qt * QT;
    const int kbase = qbase - 64;
    const int col0 = h * HDIM;
    const int tid = threadIdx.x;

    for (int f = tid; f < QT * (HDIM / 4); f += 256) {
        int r = f >> 4, c4 = (f & 15) << 2;
        float4 q4 = *(const float4*)&Q[(size_t)(qbase + r) * D_MOD + col0 + c4];
        Qt[(c4 + 0) * QT_STRIDE + r] = q4.x;
        Qt[(c4 + 1) * QT_STRIDE + r] = q4.y;
        Qt[(c4 + 2) * QT_STRIDE + r] = q4.z;
        Qt[(c4 + 3) * QT_STRIDE + r] = q4.w;
    }
    for (int f = tid; f < KW * (HDIM / 4); f += 256) {
        int j = f >> 4, c4 = (f & 15) << 2;
        int kj = kbase + j;
        float4 kv = make_float4(0.f, 0.f, 0.f, 0.f);
        float4 vv = kv;
        if (kj >= 0 && kj < S_LEN) {
            kv = *(const float4*)&K[(size_t)kj * D_MOD + col0 + c4];
            vv = *(const float4*)&V[(size_t)kj * D_MOD + col0 + c4];
        }
        Kt[(c4 + 0) * KT_STRIDE + j] = kv.x;
        Kt[(c4 + 1) * KT_STRIDE + j] = kv.y;
        Kt[(c4 + 2) * KT_STRIDE + j] = kv.z;
        Kt[(c4 + 3) * KT_STRIDE + j] = kv.w;
        *(float4*)&Vs[j * VS_STRIDE + c4] = vv;
    }
    __syncthreads();

    const int tx = tid & 15;
    const int ty = tid >> 4;
    const int m0 = ty * 4;
    const int n0s = tx * 12;

    float acc[4][12];
#pragma unroll
    for (int i = 0; i < 4; i++)
#pragma unroll
        for (int t = 0; t < 12; t++) acc[i][t] = 0.f;

#pragma unroll 2
    for (int d = 0; d < HDIM; d++) {
        float4 q4 = *(const float4*)&Qt[d * QT_STRIDE + m0];
        float4 k0 = *(const float4*)&Kt[d * KT_STRIDE + n0s];
        float4 k1 = *(const float4*)&Kt[d * KT_STRIDE + n0s + 4];
        float4 k2 = *(const float4*)&Kt[d * KT_STRIDE + n0s + 8];
        float qm[4] = {q4.x, q4.y, q4.z, q4.w};
        float kn[12] = {k0.x, k0.y, k0.z, k0.w, k1.x, k1.y, k1.z, k1.w,
                        k2.x, k2.y, k2.z, k2.w};
#pragma unroll
        for (int i = 0; i < 4; i++)
#pragma unroll
            for (int t = 0; t < 12; t++)
                acc[i][t] += qm[i] * kn[t];
    }

    float mx[4], sum[4];
#pragma unroll
    for (int i = 0; i < 4; i++) {
        int r = m0 + i;
        float m = -1e30f;
#pragma unroll
        for (int t = 0; t < 12; t++) {
            int j = n0s + t;
            int kj = kbase + j;
            bool valid = (j >= r) && (j <= r + 128) && (kj >= 0) && (kj < S_LEN);
            acc[i][t] = valid ? acc[i][t] * 0.125f : -1e30f;
            m = fmaxf(m, acc[i][t]);
        }
        mx[i] = m;
    }
#pragma unroll
    for (int i = 0; i < 4; i++) {
        mx[i] = fmaxf(mx[i], __shfl_xor_sync(0xffffffffu, mx[i], 1));
        mx[i] = fmaxf(mx[i], __shfl_xor_sync(0xffffffffu, mx[i], 2));
        mx[i] = fmaxf(mx[i], __shfl_xor_sync(0xffffffffu, mx[i], 4));
        mx[i] = fmaxf(mx[i], __shfl_xor_sync(0xffffffffu, mx[i], 8));
    }
#pragma unroll
    for (int i = 0; i < 4; i++) {
        float s = 0.f;
#pragma unroll
        for (int t = 0; t < 12; t++) {
            acc[i][t] = __expf(acc[i][t] - mx[i]);
            s += acc[i][t];
        }
        sum[i] = s;
    }
#pragma unroll
    for (int i = 0; i < 4; i++) {
        sum[i] += __shfl_xor_sync(0xffffffffu, sum[i], 1);
        sum[i] += __shfl_xor_sync(0xffffffffu, sum[i], 2);
        sum[i] += __shfl_xor_sync(0xffffffffu, sum[i], 4);
        sum[i] += __shfl_xor_sync(0xffffffffu, sum[i], 8);
        sum[i] = 1.0f / sum[i];
    }

#pragma unroll
    for (int t = 0; t < 12; t++) {
        int j = n0s + t;
        float4 p4 = make_float4(acc[0][t] * sum[0], acc[1][t] * sum[1],
                                acc[2][t] * sum[2], acc[3][t] * sum[3]);
        *(float4*)&Pt[j * PT_STRIDE + m0] = p4;
    }
    __syncthreads();

    const int n0 = tx * 4;
    float o[4][4];
#pragma unroll
    for (int i = 0; i < 4; i++)
#pragma unroll
        for (int jj = 0; jj < 4; jj++) o[i][jj] = 0.f;

#pragma unroll 4
    for (int j = 0; j < KW; j++) {
        float4 p4 = *(const float4*)&Pt[j * PT_STRIDE + m0];
        float4 v4 = *(const float4*)&Vs[j * VS_STRIDE + n0];
        float pm[4] = {p4.x, p4.y, p4.z, p4.w};
        float vn[4] = {v4.x, v4.y, v4.z, v4.w};
#pragma unroll
        for (int i = 0; i < 4; i++)
#pragma unroll
            for (int jj = 0; jj < 4; jj++)
                o[i][jj] += pm[i] * vn[jj];
    }
#pragma unroll
    for (int i = 0; i < 4; i++) {
        float4 ov = make_float4(o[i][0], o[i][1], o[i][2], o[i][3]);
        *(float4*)&ctx[(size_t)(qbase + m0 + i) * D_MOD + col0 + n0] = ov;
    }
}

// ---------------------------------------------------------------------------
extern "C" void kernel_launch(void* const* d_in, const int* in_sizes, int n_in,
                              void* d_out, int out_size) {
    const float* query = (const float*)d_in[0];
    const float* key   = (const float*)d_in[1];
    const float* value = (const float*)d_in[2];
    const float* Wq = (const float*)d_in[3];
    const float* bq = (const float*)d_in[4];
    const float* Wk = (const float*)d_in[5];
    const float* bk = (const float*)d_in[6];
    const float* Wv = (const float*)d_in[7];
    const float* bv = (const float*)d_in[8];
    const float* Wo = (const float*)d_in[9];
    const float* bo = (const float*)d_in[10];
    float* out = (float*)d_out;

    float *qp, *kp, *vp, *cp;
    __nv_bfloat16 *apk, *bpk;
    cudaGetSymbolAddress((void**)&qp, g_Q);
    cudaGetSymbolAddress((void**)&kp, g_K);
    cudaGetSymbolAddress((void**)&vp, g_V);
    cudaGetSymbolAddress((void**)&cp, g_ctx);
    cudaGetSymbolAddress((void**)&apk, g_Apk);
    cudaGetSymbolAddress((void**)&bpk, g_Bpk);
    __nv_bfloat16* apk0 = apk;
    __nv_bfloat16* apk1 = apk + (size_t)S_LEN * GK;
    __nv_bfloat16* apk2 = apk + (size_t)2 * S_LEN * GK;
    __nv_bfloat16* bpk0 = bpk;
    __nv_bfloat16* bpk1 = bpk + (size_t)D_MOD * GK;
    __nv_bfloat16* bpk2 = bpk + (size_t)2 * D_MOD * GK;

    const int gemm_smem = GSTAGES * STAGE_BYTES;   // 98304
    cudaFuncSetAttribute(gemm_mma_kernel,
                         cudaFuncAttributeMaxDynamicSharedMemorySize, gemm_smem);
    size_t attn_smem = (size_t)ATTN_SMEM_FLOATS * sizeof(float);
    cudaFuncSetAttribute(attn_kernel,
                         cudaFuncAttributeMaxDynamicSharedMemorySize, (int)attn_smem);

    // ---- Fused Q/K/V projections ----
    pack_A3_kernel<<<dim3(1536, 3), 256>>>(query, key, value, apk0, apk1, apk2);
    pack_W3_kernel<<<dim3(24, 24, 3), 256>>>(Wq, Wk, Wv, bpk0, bpk1, bpk2);
    gemm_mma_kernel<<<dim3(6, 16, 3), 256, gemm_smem>>>(
        apk0, apk1, apk2, bpk0, bpk1, bpk2, bq, bk, bv, qp, kp, vp);

    // ---- Attention ----
    dim3 agrid(S_LEN / QT, N_HEADS);
    attn_kernel<<<agrid, 256, attn_smem>>>(qp, kp, vp, cp);

    // ---- Output projection ----
    pack_A3_kernel<<<dim3(1536, 1), 256>>>(cp, cp, cp, apk0, apk0, apk0);
    pack_W3_kernel<<<dim3(24, 24, 1), 256>>>(Wo, Wo, Wo, bpk0, bpk0, bpk0);
    gemm_mma_kernel<<<dim3(6, 16, 1), 256, gemm_smem>>>(
        apk0, apk0, apk0, bpk0, bpk0, bpk0, bo, bo, bo, out, out, out);
}

// round 8
// speedup vs baseline: 1.8586x; 1.8586x over previous
#include <cuda_runtime.h>
#include <cuda_fp16.h>
#include <math.h>

// ---------------- Problem constants ----------------
#define S_LEN 2048
#define D_MOD 768
#define N_HEADS 12
#define HDIM 64
#define QT 64
#define KW 192

// ---------------- fp16 GEMM constants ----------------
#define GK 768
#define NCHUNK 12          // GK / 64
#define CHUNK_K 64

// ---------------- Scratch (no cudaMalloc allowed) ----------------
__device__ float g_Q[S_LEN * D_MOD];
__device__ float g_K[S_LEN * D_MOD];
__device__ float g_V[S_LEN * D_MOD];
__device__ float g_ctx[S_LEN * D_MOD];
__device__ __align__(1024) __half g_Apk[3][S_LEN * GK];
__device__ __align__(1024) __half g_Bpk[3][D_MOD * GK];

// ---------------- PTX helpers (base sm_103-safe: sm_80 era) ----------------
__device__ __forceinline__ unsigned smem_u32(const void* p) {
    unsigned a;
    asm("{ .reg .u64 t; cvta.to.shared.u64 t, %1; cvt.u32.u64 %0, t; }"
        : "=r"(a) : "l"(p));
    return a;
}
__device__ __forceinline__ void cp_async16(unsigned saddr, const void* gptr) {
    asm volatile("cp.async.cg.shared.global [%0], [%1], 16;"
                 :: "r"(saddr), "l"(gptr));
}
__device__ __forceinline__ void cp_commit() {
    asm volatile("cp.async.commit_group;");
}
__device__ __forceinline__ void cp_wait1() {
    asm volatile("cp.async.wait_group 1;");
}
__device__ __forceinline__ void ldsm_x4(unsigned* r, unsigned addr) {
    asm volatile("ldmatrix.sync.aligned.m8n8.x4.shared.b16 {%0,%1,%2,%3}, [%4];"
                 : "=r"(r[0]), "=r"(r[1]), "=r"(r[2]), "=r"(r[3]) : "r"(addr));
}
__device__ __forceinline__ void mma16816(float* c, const unsigned* a, const unsigned* b) {
    asm volatile(
        "mma.sync.aligned.m16n8k16.row.col.f32.f16.f16.f32 "
        "{%0,%1,%2,%3}, {%4,%5,%6,%7}, {%8,%9}, {%0,%1,%2,%3};"
        : "+f"(c[0]), "+f"(c[1]), "+f"(c[2]), "+f"(c[3])
        : "r"(a[0]), "r"(a[1]), "r"(a[2]), "r"(a[3]), "r"(b[0]), "r"(b[1]));
}
__device__ __forceinline__ unsigned packh2(__half a, __half b) {
    __half2 t = __halves2half2(a, b);
    return *(unsigned*)&t;
}

// ---------------------------------------------------------------------------
// Pack A (up to 3 inputs): fp32 [2048x768] -> fp16 [2048][768]
// ---------------------------------------------------------------------------
__global__ __launch_bounds__(256) void pack_A3_kernel(
    const float* __restrict__ A0, const float* __restrict__ A1,
    const float* __restrict__ A2,
    __half* __restrict__ O0, __half* __restrict__ O1, __half* __restrict__ O2)
{
    const int z = blockIdx.y;
    const float* A = (z == 0) ? A0 : (z == 1) ? A1 : A2;
    __half* O = (z == 0) ? O0 : (z == 1) ? O1 : O2;

    int g = blockIdx.x * 256 + threadIdx.x;     // < 2048*192
    int idx4 = g * 4;
    float4 v = *(const float4*)&A[idx4];
    uint2 hw = make_uint2(packh2(__float2half(v.x), __float2half(v.y)),
                          packh2(__float2half(v.z), __float2half(v.w)));
    *(uint2*)&O[idx4] = hw;
}

// ---------------------------------------------------------------------------
// Pack W (up to 3 weights): fp32 [K=768][N=768] transposed -> fp16 [768 n][768 k]
// via 32x32 smem transpose, 8-byte stores.
// ---------------------------------------------------------------------------
__global__ __launch_bounds__(256) void pack_W3_kernel(
    const float* __restrict__ W0, const float* __restrict__ W1,
    const float* __restrict__ W2,
    __half* __restrict__ O0, __half* __restrict__ O1, __half* __restrict__ O2)
{
    const int z = blockIdx.z;
    const float* W = (z == 0) ? W0 : (z == 1) ? W1 : W2;
    __half* O = (z == 0) ? O0 : (z == 1) ? O1 : O2;

    __shared__ float t[32][33];
    const int tx = threadIdx.x & 31;
    const int ty = threadIdx.x >> 5;           // 0..7
    const int k0 = blockIdx.y * 32;
    const int n0 = blockIdx.x * 32;
#pragma unroll
    for (int i = 0; i < 4; i++)
        t[ty + i * 8][tx] = W[(size_t)(k0 + ty + i * 8) * D_MOD + n0 + tx];
    __syncthreads();

    const int nl = threadIdx.x >> 3;           // 0..31
    const int kg = (threadIdx.x & 7) * 4;      // 0..28
    uint2 hw = make_uint2(
        packh2(__float2half(t[kg + 0][nl]), __float2half(t[kg + 1][nl])),
        packh2(__float2half(t[kg + 2][nl]), __float2half(t[kg + 3][nl])));
    *(uint2*)&O[(size_t)(n0 + nl) * GK + k0 + kg] = hw;
}

// ---------------------------------------------------------------------------
// HMMA fp16 GEMM (batched over blockIdx.z): C = A @ W^T + bias (fp32 accum)
// CTA 128x128, 8 warps (warp tile 64x32), K-chunk 64, 3-stage cp.async.
// ---------------------------------------------------------------------------
#define GSTAGES 3
#define STAGE_BYTES 32768   // A 16KB + B 16KB

__global__ __launch_bounds__(256, 2) void gemm_mma_kernel(
    const __half* __restrict__ a0, const __half* __restrict__ a1,
    const __half* __restrict__ a2,
    const __half* __restrict__ b0, const __half* __restrict__ b1,
    const __half* __restrict__ b2,
    const float* __restrict__ bias0, const float* __restrict__ bias1,
    const float* __restrict__ bias2,
    float* __restrict__ c0, float* __restrict__ c1, float* __restrict__ c2)
{
    const int z = blockIdx.z;
    const __half* Apk = (z == 0) ? a0 : (z == 1) ? a1 : a2;
    const __half* Bpk = (z == 0) ? b0 : (z == 1) ? b1 : b2;
    const float* bias = (z == 0) ? bias0 : (z == 1) ? bias1 : bias2;
    float* C = (z == 0) ? c0 : (z == 1) ? c1 : c2;

    extern __shared__ char smem[];
    const unsigned sb = smem_u32(smem);

    const int tid  = threadIdx.x;
    const int wid  = tid >> 5;
    const int lane = tid & 31;
    const int wm   = wid & 1;
    const int wn   = wid >> 1;
    const int mBase = blockIdx.y * 128;
    const int nBase = blockIdx.x * 128;

    const __half* aSrc = Apk + (size_t)mBase * GK;
    const __half* bSrc = Bpk + (size_t)nBase * GK;

    const int lrow = tid >> 1;
    const int lch0 = (tid & 1) << 2;
    auto load_stage = [&](int stage, int chunk) {
        unsigned sA = sb + stage * STAGE_BYTES;
        unsigned sB = sA + 16384;
        const __half* ga = aSrc + (size_t)lrow * GK + chunk * CHUNK_K + lch0 * 8;
        const __half* gb = bSrc + (size_t)lrow * GK + chunk * CHUNK_K + lch0 * 8;
        unsigned rbase = lrow * 128;
        unsigned rx = lrow & 7;
#pragma unroll
        for (int c = 0; c < 4; c++) {
            unsigned swoff = rbase + (((lch0 + c) ^ rx) << 4);
            cp_async16(sA + swoff, ga + c * 8);
            cp_async16(sB + swoff, gb + c * 8);
        }
    };

    float acc[4][4][4];
#pragma unroll
    for (int i = 0; i < 4; i++)
#pragma unroll
        for (int j = 0; j < 4; j++)
#pragma unroll
            for (int r = 0; r < 4; r++) acc[i][j][r] = 0.f;

    load_stage(0, 0); cp_commit();
    load_stage(1, 1); cp_commit();

    const int arow_l = wm * 64 + (lane & 15);
    const int asel   = lane >> 4;
    const int brow_l = wn * 32 + ((lane & 16) ? 8 : 0) + (lane & 7);
    const int bsel   = (lane >> 3) & 1;

    for (int c = 0; c < NCHUNK; c++) {
        cp_wait1();
        __syncthreads();
        if (c + 2 < NCHUNK) { load_stage((c + 2) % GSTAGES, c + 2); cp_commit(); }
        else                { cp_commit(); }

        unsigned sA = sb + (c % GSTAGES) * STAGE_BYTES;
        unsigned sB = sA + 16384;

#pragma unroll
        for (int ks = 0; ks < 4; ks++) {
            unsigned afr[4][4];
#pragma unroll
            for (int i = 0; i < 4; i++) {
                int row = arow_l + i * 16;
                int ch = 2 * ks + asel;
                ldsm_x4(afr[i], sA + row * 128 + ((ch ^ (row & 7)) << 4));
            }
            unsigned bfr[2][4];
#pragma unroll
            for (int p = 0; p < 2; p++) {
                int row = brow_l + p * 16;
                int ch = 2 * ks + bsel;
                ldsm_x4(bfr[p], sB + row * 128 + ((ch ^ (row & 7)) << 4));
            }
#pragma unroll
            for (int i = 0; i < 4; i++) {
#pragma unroll
                for (int p = 0; p < 2; p++) {
                    mma16816(acc[i][2 * p],     afr[i], &bfr[p][0]);
                    mma16816(acc[i][2 * p + 1], afr[i], &bfr[p][2]);
                }
            }
        }
    }

#pragma unroll
    for (int i = 0; i < 4; i++) {
        int row = mBase + wm * 64 + i * 16 + (lane >> 2);
#pragma unroll
        for (int j = 0; j < 4; j++) {
            int col = nBase + wn * 32 + j * 8 + (lane & 3) * 2;
            float2 b2 = *(const float2*)&bias[col];
            float2 o0 = make_float2(acc[i][j][0] + b2.x, acc[i][j][1] + b2.y);
            float2 o1 = make_float2(acc[i][j][2] + b2.x, acc[i][j][3] + b2.y);
            *(float2*)&C[(size_t)row * D_MOD + col] = o0;
            *(float2*)&C[(size_t)(row + 8) * D_MOD + col] = o1;
        }
    }
}

// ---------------------------------------------------------------------------
// Sliding-window attention v3: smem squeezed to 112KB for 2 CTAs/SM.
//   region1: Qt[64 d][64] + Kt[64 d][192]; Pt[192][68] overlays region1.
//   Vs[192][64] separate. Q/K loaders remapped: 32 lanes -> 32 distinct rows
//   (conflict-free transposed stores).
// ---------------------------------------------------------------------------
#define QT_STRIDE 64
#define KT_STRIDE 192
#define VS_STRIDE 64
#define PT_STRIDE 68
#define ATTN_SMEM_FLOATS (HDIM*QT_STRIDE + HDIM*KT_STRIDE + KW*VS_STRIDE)  // 28672

__global__ __launch_bounds__(256, 2) void attn_kernel(
    const float* __restrict__ Q, const float* __restrict__ K,
    const float* __restrict__ V, float* __restrict__ ctx)
{
    extern __shared__ float sm[];
    float* Qt = sm;                              // [64 d][64]
    float* Kt = sm + HDIM * QT_STRIDE;           // [64 d][192]
    float* Pt = sm;                              // overlay [192 j][68] (13056 <= 16384)
    float* Vs = sm + HDIM * QT_STRIDE + HDIM * KT_STRIDE;   // [192 j][64]

    const int qt = blockIdx.x;
    const int h  = blockIdx.y;
    const int qbase = qt * QT;
    const int kbase = qbase - 64;
    const int col0 = h * HDIM;
    const int tid = threadIdx.x;

    // Q transposed: lanes spread over rows -> conflict-free scalar stores
#pragma unroll
    for (int it = 0; it < 4; it++) {
        int idx = it * 256 + tid;                // 0..1023
        int r = idx & 63;
        int cg = idx >> 6;                       // 0..15
        float4 q4 = *(const float4*)&Q[(size_t)(qbase + r) * D_MOD + col0 + cg * 4];
        Qt[(cg * 4 + 0) * QT_STRIDE + r] = q4.x;
        Qt[(cg * 4 + 1) * QT_STRIDE + r] = q4.y;
        Qt[(cg * 4 + 2) * QT_STRIDE + r] = q4.z;
        Qt[(cg * 4 + 3) * QT_STRIDE + r] = q4.w;
    }
    // K transposed: same row-spread mapping
#pragma unroll
    for (int it = 0; it < 12; it++) {
        int idx = it * 256 + tid;                // 0..3071
        int j = idx % 192;
        int cg = idx / 192;                      // 0..15
        int kj = kbase + j;
        float4 kv = make_float4(0.f, 0.f, 0.f, 0.f);
        if (kj >= 0 && kj < S_LEN)
            kv = *(const float4*)&K[(size_t)kj * D_MOD + col0 + cg * 4];
        Kt[(cg * 4 + 0) * KT_STRIDE + j] = kv.x;
        Kt[(cg * 4 + 1) * KT_STRIDE + j] = kv.y;
        Kt[(cg * 4 + 2) * KT_STRIDE + j] = kv.z;
        Kt[(cg * 4 + 3) * KT_STRIDE + j] = kv.w;
    }
    // V row-major: lanes spread over columns (coalesced global, 128-bit stores)
#pragma unroll
    for (int it = 0; it < 12; it++) {
        int idx = it * 256 + tid;
        int j = idx >> 4;
        int c4 = (idx & 15) << 2;
        int kj = kbase + j;
        float4 vv = make_float4(0.f, 0.f, 0.f, 0.f);
        if (kj >= 0 && kj < S_LEN)
            vv = *(const float4*)&V[(size_t)kj * D_MOD + col0 + c4];
        *(float4*)&Vs[j * VS_STRIDE + c4] = vv;
    }
    __syncthreads();

    const int tx = tid & 15;
    const int ty = tid >> 4;
    const int m0 = ty * 4;
    const int n0s = tx * 12;

    float acc[4][12];
#pragma unroll
    for (int i = 0; i < 4; i++)
#pragma unroll
        for (int t = 0; t < 12; t++) acc[i][t] = 0.f;

#pragma unroll 2
    for (int d = 0; d < HDIM; d++) {
        float4 q4 = *(const float4*)&Qt[d * QT_STRIDE + m0];
        float4 k0 = *(const float4*)&Kt[d * KT_STRIDE + n0s];
        float4 k1 = *(const float4*)&Kt[d * KT_STRIDE + n0s + 4];
        float4 k2 = *(const float4*)&Kt[d * KT_STRIDE + n0s + 8];
        float qm[4] = {q4.x, q4.y, q4.z, q4.w};
        float kn[12] = {k0.x, k0.y, k0.z, k0.w, k1.x, k1.y, k1.z, k1.w,
                        k2.x, k2.y, k2.z, k2.w};
#pragma unroll
        for (int i = 0; i < 4; i++)
#pragma unroll
            for (int t = 0; t < 12; t++)
                acc[i][t] += qm[i] * kn[t];
    }

    float mx[4], sum[4];
#pragma unroll
    for (int i = 0; i < 4; i++) {
        int r = m0 + i;
        float m = -1e30f;
#pragma unroll
        for (int t = 0; t < 12; t++) {
            int j = n0s + t;
            int kj = kbase + j;
            bool valid = (j >= r) && (j <= r + 128) && (kj >= 0) && (kj < S_LEN);
            acc[i][t] = valid ? acc[i][t] * 0.125f : -1e30f;
            m = fmaxf(m, acc[i][t]);
        }
        mx[i] = m;
    }
#pragma unroll
    for (int i = 0; i < 4; i++) {
        mx[i] = fmaxf(mx[i], __shfl_xor_sync(0xffffffffu, mx[i], 1));
        mx[i] = fmaxf(mx[i], __shfl_xor_sync(0xffffffffu, mx[i], 2));
        mx[i] = fmaxf(mx[i], __shfl_xor_sync(0xffffffffu, mx[i], 4));
        mx[i] = fmaxf(mx[i], __shfl_xor_sync(0xffffffffu, mx[i], 8));
    }
#pragma unroll
    for (int i = 0; i < 4; i++) {
        float s = 0.f;
#pragma unroll
        for (int t = 0; t < 12; t++) {
            acc[i][t] = __expf(acc[i][t] - mx[i]);
            s += acc[i][t];
        }
        sum[i] = s;
    }
#pragma unroll
    for (int i = 0; i < 4; i++) {
        sum[i] += __shfl_xor_sync(0xffffffffu, sum[i], 1);
        sum[i] += __shfl_xor_sync(0xffffffffu, sum[i], 2);
        sum[i] += __shfl_xor_sync(0xffffffffu, sum[i], 4);
        sum[i] += __shfl_xor_sync(0xffffffffu, sum[i], 8);
        sum[i] = 1.0f / sum[i];
    }

    // Pt overlays Qt/Kt: make sure everyone finished reading them.
    __syncthreads();
#pragma unroll
    for (int t = 0; t < 12; t++) {
        int j = n0s + t;
        float4 p4 = make_float4(acc[0][t] * sum[0], acc[1][t] * sum[1],
                                acc[2][t] * sum[2], acc[3][t] * sum[3]);
        *(float4*)&Pt[j * PT_STRIDE + m0] = p4;
    }
    __syncthreads();

    const int n0 = tx * 4;
    float o[4][4];
#pragma unroll
    for (int i = 0; i < 4; i++)
#pragma unroll
        for (int jj = 0; jj < 4; jj++) o[i][jj] = 0.f;

#pragma unroll 4
    for (int j = 0; j < KW; j++) {
        float4 p4 = *(const float4*)&Pt[j * PT_STRIDE + m0];
        float4 v4 = *(const float4*)&Vs[j * VS_STRIDE + n0];
        float pm[4] = {p4.x, p4.y, p4.z, p4.w};
        float vn[4] = {v4.x, v4.y, v4.z, v4.w};
#pragma unroll
        for (int i = 0; i < 4; i++)
#pragma unroll
            for (int jj = 0; jj < 4; jj++)
                o[i][jj] += pm[i] * vn[jj];
    }
#pragma unroll
    for (int i = 0; i < 4; i++) {
        float4 ov = make_float4(o[i][0], o[i][1], o[i][2], o[i][3]);
        *(float4*)&ctx[(size_t)(qbase + m0 + i) * D_MOD + col0 + n0] = ov;
    }
}

// ---------------------------------------------------------------------------
extern "C" void kernel_launch(void* const* d_in, const int* in_sizes, int n_in,
                              void* d_out, int out_size) {
    const float* query = (const float*)d_in[0];
    const float* key   = (const float*)d_in[1];
    const float* value = (const float*)d_in[2];
    const float* Wq = (const float*)d_in[3];
    const float* bq = (const float*)d_in[4];
    const float* Wk = (const float*)d_in[5];
    const float* bk = (const float*)d_in[6];
    const float* Wv = (const float*)d_in[7];
    const float* bv = (const float*)d_in[8];
    const float* Wo = (const float*)d_in[9];
    const float* bo = (const float*)d_in[10];
    float* out = (float*)d_out;

    float *qp, *kp, *vp, *cp;
    __half *apk, *bpk;
    cudaGetSymbolAddress((void**)&qp, g_Q);
    cudaGetSymbolAddress((void**)&kp, g_K);
    cudaGetSymbolAddress((void**)&vp, g_V);
    cudaGetSymbolAddress((void**)&cp, g_ctx);
    cudaGetSymbolAddress((void**)&apk, g_Apk);
    cudaGetSymbolAddress((void**)&bpk, g_Bpk);
    __half* apk0 = apk;
    __half* apk1 = apk + (size_t)S_LEN * GK;
    __half* apk2 = apk + (size_t)2 * S_LEN * GK;
    __half* bpk0 = bpk;
    __half* bpk1 = bpk + (size_t)D_MOD * GK;
    __half* bpk2 = bpk + (size_t)2 * D_MOD * GK;

    const int gemm_smem = GSTAGES * STAGE_BYTES;   // 98304
    cudaFuncSetAttribute(gemm_mma_kernel,
                         cudaFuncAttributeMaxDynamicSharedMemorySize, gemm_smem);
    const int attn_smem = ATTN_SMEM_FLOATS * sizeof(float);   // 114688
    cudaFuncSetAttribute(attn_kernel,
                         cudaFuncAttributeMaxDynamicSharedMemorySize, attn_smem);

    // ---- Fused Q/K/V projections ----
    pack_A3_kernel<<<dim3(1536, 3), 256>>>(query, key, value, apk0, apk1, apk2);
    pack_W3_kernel<<<dim3(24, 24, 3), 256>>>(Wq, Wk, Wv, bpk0, bpk1, bpk2);
    gemm_mma_kernel<<<dim3(6, 16, 3), 256, gemm_smem>>>(
        apk0, apk1, apk2, bpk0, bpk1, bpk2, bq, bk, bv, qp, kp, vp);

    // ---- Attention ----
    dim3 agrid(S_LEN / QT, N_HEADS);
    attn_kernel<<<agrid, 256, attn_smem>>>(qp, kp, vp, cp);

    // ---- Output projection ----
    pack_A3_kernel<<<dim3(1536, 1), 256>>>(cp, cp, cp, apk0, apk0, apk0);
    pack_W3_kernel<<<dim3(24, 24, 1), 256>>>(Wo, Wo, Wo, bpk0, bpk0, bpk0);
    gemm_mma_kernel<<<dim3(6, 16, 1), 256, gemm_smem>>>(
        apk0, apk0, apk0, bpk0, bpk0, bpk0, bo, bo, bo, out, out, out);
}